// round 16
// baseline (speedup 1.0000x reference)
#include <cuda_runtime.h>
#include <cuda_fp16.h>
#include <cstdint>

#define HH 256
#define FF 64
#define LL 512
#define BB 256

// ---------------- device scratch ----------------
__device__ __half g_Wh[8][128][256];
__device__ __half g_Wx[8][128][256];
__device__ __half g_Wlin16[FF * HH];
__device__ float  g_bias[1024];
__device__ float  g_po0[BB][FF];
__device__ float  g_corr0[BB][1024];
__device__ __half g_hall[(size_t)LL * BB * HH];

// ---------------- ptx helpers ----------------
__device__ __forceinline__ void mma16816(float* d, uint32_t a0, uint32_t a1,
                                         uint32_t a2, uint32_t a3,
                                         uint32_t b0, uint32_t b1) {
    asm volatile(
        "mma.sync.aligned.m16n8k16.row.col.f32.f16.f16.f32 "
        "{%0,%1,%2,%3}, {%4,%5,%6,%7}, {%8,%9}, {%0,%1,%2,%3};"
        : "+f"(d[0]), "+f"(d[1]), "+f"(d[2]), "+f"(d[3])
        : "r"(a0), "r"(a1), "r"(a2), "r"(a3), "r"(b0), "r"(b1));
}
__device__ __forceinline__ void ldsm4(uint32_t& r0, uint32_t& r1, uint32_t& r2,
                                      uint32_t& r3, uint32_t a) {
    asm volatile("ldmatrix.sync.aligned.m8n8.x4.shared.b16 {%0,%1,%2,%3}, [%4];"
                 : "=r"(r0), "=r"(r1), "=r"(r2), "=r"(r3) : "r"(a));
}
__device__ __forceinline__ uint32_t s2u(const void* p) {
    uint32_t a;
    asm("{.reg .u64 t; cvta.to.shared.u64 t, %1; cvt.u32.u64 %0, t;}"
        : "=r"(a) : "l"(p));
    return a;
}
__device__ __forceinline__ uint32_t mapa_(uint32_t a, uint32_t r) {
    uint32_t d;
    asm("mapa.shared::cluster.u32 %0, %1, %2;" : "=r"(d) : "r"(a), "r"(r));
    return d;
}
__device__ __forceinline__ void mbar_init(uint32_t a, uint32_t n) {
    asm volatile("mbarrier.init.shared.b64 [%0], %1;" :: "r"(a), "r"(n) : "memory");
}
__device__ __forceinline__ void mbar_expect(uint32_t a, uint32_t tx) {
    asm volatile("mbarrier.arrive.expect_tx.shared.b64 _, [%0], %1;"
                 :: "r"(a), "r"(tx) : "memory");
}
__device__ __forceinline__ void st_async32(uint32_t dst, uint32_t v, uint32_t mb) {
    asm volatile(
        "st.async.shared::cluster.mbarrier::complete_tx::bytes.b32 [%0], %1, [%2];"
        :: "r"(dst), "r"(v), "r"(mb) : "memory");
}
__device__ __forceinline__ void mbar_wait(uint32_t a, uint32_t par) {
    uint32_t done;
    asm volatile(
        "{\n\t.reg .pred p;\n\t"
        "mbarrier.try_wait.parity.acquire.cta.shared::cta.b64 p, [%1], %2;\n\t"
        "selp.b32 %0, 1, 0, p;\n\t}"
        : "=r"(done) : "r"(a), "r"(par) : "memory");
    if (!done) {
        asm volatile(
            "{\n\t.reg .pred P1;\n\t"
            "W_%=:\n\t"
            "mbarrier.try_wait.parity.acquire.cta.shared::cta.b64 P1, [%0], %1, 0x989680;\n\t"
            "@P1 bra.uni D_%=;\n\t"
            "bra.uni W_%=;\n\t"
            "D_%=:\n\t}"
            :: "r"(a), "r"(par) : "memory");
    }
}
__device__ __forceinline__ float tanhf_(float x) {
    float r;
    asm("tanh.approx.f32 %0, %1;" : "=f"(r) : "f"(x));
    return r;
}
__device__ __forceinline__ float sigmoid_(float x) {
    return fmaf(tanhf_(0.5f * x), 0.5f, 0.5f);
}

// ---------------- prep kernels ----------------
__global__ void prep_all(const float* __restrict__ W_ih, const float* __restrict__ W_hh,
                         const float* __restrict__ W_lin, const float* __restrict__ b_ih,
                         const float* __restrict__ b_hh, const float* __restrict__ b_lin,
                         const float* __restrict__ h0) {
    if (blockIdx.x < 2112) {
        int id = blockIdx.x * 256 + threadIdx.x;
        if (id < 262144) {          // fused Wh (permuted slices)
            int k = id & 255, ln = (id >> 8) & 127, s = id >> 15;
            int n = (ln >> 5) * 256 + s * 32 + (ln & 31);
            float v = W_hh[n * HH + k];
            float acc = 0.f;
#pragma unroll 8
            for (int f = 0; f < FF; f++)
                acc += W_lin[f * HH + k] * W_ih[n * (FF + HH) + f];
            g_Wh[s][ln][k] = __float2half(v + acc);
        } else if (id < 524288) {   // Wx (permuted slices, same layout as Wh)
            int j = id - 262144;
            int k = j & 255, ln = (j >> 8) & 127, s = j >> 15;
            int n = (ln >> 5) * 256 + s * 32 + (ln & 31);
            g_Wx[s][ln][k] = __float2half(W_ih[n * (FF + HH) + FF + k]);
        } else if (id < 540672) {
            g_Wlin16[id - 524288] = __float2half(W_lin[id - 524288]);
        }
    } else if (blockIdx.x < 4160) {
        int wid = (blockIdx.x - 2112) * 8 + (threadIdx.x >> 5);  // po0
        int lane = threadIdx.x & 31;
        int b = wid >> 6, f = wid & 63;
        float acc = 0.f;
#pragma unroll
        for (int q = 0; q < 8; q++) {
            int k = lane + 32 * q;
            acc += h0[b * HH + k] * W_lin[f * HH + k];
        }
#pragma unroll
        for (int o = 16; o; o >>= 1) acc += __shfl_xor_sync(~0u, acc, o);
        if (!lane) g_po0[b][f] = acc + b_lin[f];
    } else {
        int n = (blockIdx.x - 4160) * 256 + threadIdx.x;  // bias
        float v = b_ih[n] + b_hh[n];
#pragma unroll 8
        for (int f = 0; f < FF; f++) v += b_lin[f] * W_ih[n * (FF + HH) + f];
        g_bias[n] = v;
    }
}

__global__ void prep_corr0(const float* __restrict__ W_ih) {
    int wid = blockIdx.x * 8 + (threadIdx.x >> 5);
    int lane = threadIdx.x & 31;
    int b = wid >> 10, n = wid & 1023;
    float acc = W_ih[n * (FF + HH) + lane] * g_po0[b][lane] +
                W_ih[n * (FF + HH) + 32 + lane] * g_po0[b][32 + lane];
#pragma unroll
    for (int o = 16; o; o >>= 1) acc += __shfl_xor_sync(~0u, acc, o);
    if (!lane) g_corr0[b][n] = -acc;
}

// ---------------- main recurrent kernel (launch idx 2) ----------------
// Fused x-GEMM: gates_x(t+1) computed in the DSMEM-transit window after sends.
// Sync protocol byte-identical to the proven R13 kernel.
static constexpr int OFF_WH   = 0;                      // 67584
static constexpr int OFF_WX   = 67584;                  // 67584
static constexpr int HS_BUF   = 8448;                   // 16*528
static constexpr int OFF_HS   = 135168;                 // 2 phases -> 16896
static constexpr int OFF_GSMH = OFF_HS + 2 * HS_BUF;    // 152064; 2 x 8448
static constexpr int OFF_GSMX = OFF_GSMH + 2 * 8448;    // 168960; 2 x 8448
static constexpr int OFF_XS   = OFF_GSMX + 2 * 8448;    // 185856; 2 x 8448
static constexpr int OFF_MBAR = OFF_XS + 2 * 8448;      // 202752; 2 mbars
static constexpr int SMEM_MAIN = OFF_MBAR + 64;

__global__ void __cluster_dims__(8, 1, 1) __launch_bounds__(256, 1)
lstm_main(const float* __restrict__ h0, const float* __restrict__ c0in,
          const float* __restrict__ x) {
    extern __shared__ char smem[];
    __half* Wh_s = (__half*)(smem + OFF_WH);
    __half* Wx_s = (__half*)(smem + OFF_WX);
    __half* h_s0 = (__half*)(smem + OFF_HS);

    const uint32_t smem_u = s2u(smem);
    const uint32_t mbarB = smem_u + OFF_MBAR;

    int tid = threadIdx.x;
    int m = blockIdx.x >> 3, s = blockIdx.x & 7;
    int warp = tid >> 5, lane = tid & 31;

    if (tid < 2) mbar_init(mbarB + tid * 8, 1);

    // resident weight slices (Wh + Wx)
    for (int i = tid; i < 128 * 32; i += 256) {
        int row = i >> 5, c8 = i & 31;
        *(uint4*)(Wh_s + row * 264 + c8 * 8) = *(const uint4*)(&g_Wh[s][row][c8 * 8]);
        *(uint4*)(Wx_s + row * 264 + c8 * 8) = *(const uint4*)(&g_Wx[s][row][c8 * 8]);
    }
    // h_s[phase0] <- h0
    for (int i = tid; i < 16 * 64; i += 256) {
        int row = i >> 6, c4 = i & 63;
        float4 v = *(const float4*)(h0 + (size_t)(m * 16 + row) * HH + c4 * 4);
        __half* d = h_s0 + row * 264 + c4 * 4;
        d[0] = __float2half(v.x); d[1] = __float2half(v.y);
        d[2] = __float2half(v.z); d[3] = __float2half(v.w);
    }
    // x(0) -> x_s[0]
    for (int i = tid; i < 16 * 64; i += 256) {
        int row = i >> 6, c4 = i & 63;
        float4 v = *(const float4*)(x + ((size_t)(m * 16 + row) * LL + 0) * HH + c4 * 4);
        __half2 h01 = __floats2half2_rn(v.x, v.y);
        __half2 h23 = __floats2half2_rn(v.z, v.w);
        *(uint2*)((__half*)(smem + OFF_XS) + row * 264 + c4 * 4) =
            make_uint2(*(uint32_t*)&h01, *(uint32_t*)&h23);
    }
    // cell state + per-thread constants
    int b = tid >> 4, up = tid & 15;
    int bg = m * 16 + b;
    float2 cv = *(const float2*)(c0in + (size_t)bg * HH + s * 32 + 2 * up);
    float cst0 = cv.x, cst1 = cv.y;
    float2 bsI = *(const float2*)(g_bias + s * 32 + 2 * up);
    float2 bsF = *(const float2*)(g_bias + 256 + s * 32 + 2 * up);
    float2 bsG = *(const float2*)(g_bias + 512 + s * 32 + 2 * up);
    float2 bsO = *(const float2*)(g_bias + 768 + s * 32 + 2 * up);
    float2 crI = *(const float2*)(&g_corr0[bg][s * 32 + 2 * up]);
    float2 crF = *(const float2*)(&g_corr0[bg][256 + s * 32 + 2 * up]);
    float2 crG = *(const float2*)(&g_corr0[bg][512 + s * 32 + 2 * up]);
    float2 crO = *(const float2*)(&g_corr0[bg][768 + s * 32 + 2 * up]);
    __syncthreads();

    // Wh fragments resident in registers
    uint32_t Bf[16][4];
    const uint32_t bBoff =
        (16 * warp + (lane & 7) + ((lane >> 4) << 3)) * 528 +
        (((lane >> 3) & 1) << 4);
    {
        const uint32_t bB = smem_u + OFF_WH + bBoff;
#pragma unroll
        for (int kk = 0; kk < 16; kk++)
            ldsm4(Bf[kk][0], Bf[kk][1], Bf[kk][2], Bf[kk][3], bB + kk * 32);
    }
    const uint32_t bX = smem_u + OFF_WX + bBoff;
    const uint32_t aOff = (lane & 15) * 528 + (lane >> 4) * 16;
    uint32_t rb[8], rm[8];
    {
        uint32_t dstoff = b * 528 + (s * 32 + 2 * up) * 2;
#pragma unroll
        for (int r = 0; r < 8; r++) {
            rb[r] = mapa_(smem_u + OFF_HS, r) + dstoff;
            rm[r] = mapa_(mbarB, r);
        }
    }
    const int g = lane >> 2, tig = lane & 3;

    // prologue: gates_x(0) -> gsm_x[0]
    {
        float ax0[4] = {0.f, 0.f, 0.f, 0.f};
        float ax1[4] = {0.f, 0.f, 0.f, 0.f};
        const uint32_t aX = smem_u + OFF_XS + aOff;
        uint32_t a0, a1, a2, a3, b0, b1, b2, b3;
#pragma unroll
        for (int kk = 0; kk < 16; kk++) {
            ldsm4(a0, a1, a2, a3, aX + kk * 32);
            ldsm4(b0, b1, b2, b3, bX + kk * 32);
            mma16816(ax0, a0, a1, a2, a3, b0, b1);
            mma16816(ax1, a0, a1, a2, a3, b2, b3);
        }
        float* gx0 = (float*)(smem + OFF_GSMX);
        int c0c = 16 * warp + 2 * tig;
        *(float2*)(gx0 + g * 132 + c0c) = make_float2(ax0[0], ax0[1]);
        *(float2*)(gx0 + (g + 8) * 132 + c0c) = make_float2(ax0[2], ax0[3]);
        *(float2*)(gx0 + g * 132 + c0c + 8) = make_float2(ax1[0], ax1[1]);
        *(float2*)(gx0 + (g + 8) * 132 + c0c + 8) = make_float2(ax1[2], ax1[3]);
    }
    int ph0 = 0, ph1 = 0;

    asm volatile("barrier.cluster.arrive.aligned;" ::: "memory");
    asm volatile("barrier.cluster.wait.aligned;" ::: "memory");

#pragma unroll 1
    for (int t = 0; t < LL; t++) {
        const int cur = t & 1, nxt = cur ^ 1;
        // stage x(t+1) -> x_s[nxt] (LDG latency overlaps the wait below)
        if (t < LL - 1) {
            __half* xd = (__half*)(smem + OFF_XS + nxt * 8448);
            for (int i = tid; i < 16 * 64; i += 256) {
                int row = i >> 6, c4 = i & 63;
                float4 v = *(const float4*)(
                    x + ((size_t)(m * 16 + row) * LL + (t + 1)) * HH + c4 * 4);
                __half2 h01 = __floats2half2_rn(v.x, v.y);
                __half2 h23 = __floats2half2_rn(v.z, v.w);
                *(uint2*)(xd + row * 264 + c4 * 4) =
                    make_uint2(*(uint32_t*)&h01, *(uint32_t*)&h23);
            }
        }
        if (tid == 0 && t < LL - 1) mbar_expect(mbarB + nxt * 8, 8192);
        if (t > 0) {
            if (cur) { mbar_wait(mbarB + 8, (uint32_t)ph1); ph1 ^= 1; }
            else     { mbar_wait(mbarB,     (uint32_t)ph0); ph0 ^= 1; }
        }

        // h-part MMA
        float acc0[4] = {0.f, 0.f, 0.f, 0.f};
        float acc1[4] = {0.f, 0.f, 0.f, 0.f};
        const uint32_t aH = smem_u + OFF_HS + cur * HS_BUF + aOff;
        uint32_t a0, a1, a2, a3;
#pragma unroll
        for (int kk = 0; kk < 16; kk++) {
            ldsm4(a0, a1, a2, a3, aH + kk * 32);
            mma16816(acc0, a0, a1, a2, a3, Bf[kk][0], Bf[kk][1]);
            mma16816(acc1, a0, a1, a2, a3, Bf[kk][2], Bf[kk][3]);
        }
        float* gsmc = (float*)(smem + OFF_GSMH + cur * 8448);
        int c0c = 16 * warp + 2 * tig;
        *(float2*)(gsmc + g * 132 + c0c) = make_float2(acc0[0], acc0[1]);
        *(float2*)(gsmc + (g + 8) * 132 + c0c) = make_float2(acc0[2], acc0[3]);
        *(float2*)(gsmc + g * 132 + c0c + 8) = make_float2(acc1[0], acc1[1]);
        *(float2*)(gsmc + (g + 8) * 132 + c0c + 8) = make_float2(acc1[2], acc1[3]);
        __syncthreads();

        // cell (reads gsm_h[cur] + gsm_x[cur] + bias regs)
        {
            float* gxc = (float*)(smem + OFF_GSMX + cur * 8448);
            float2 gi = *(const float2*)(gsmc + b * 132 + 2 * up);
            float2 gf = *(const float2*)(gsmc + b * 132 + 32 + 2 * up);
            float2 gg = *(const float2*)(gsmc + b * 132 + 64 + 2 * up);
            float2 go = *(const float2*)(gsmc + b * 132 + 96 + 2 * up);
            float2 xi = *(const float2*)(gxc + b * 132 + 2 * up);
            float2 xf = *(const float2*)(gxc + b * 132 + 32 + 2 * up);
            float2 xg = *(const float2*)(gxc + b * 132 + 64 + 2 * up);
            float2 xo = *(const float2*)(gxc + b * 132 + 96 + 2 * up);
            float iv0 = gi.x + xi.x + bsI.x, iv1 = gi.y + xi.y + bsI.y;
            float fv0 = gf.x + xf.x + bsF.x, fv1 = gf.y + xf.y + bsF.y;
            float gv0 = gg.x + xg.x + bsG.x, gv1 = gg.y + xg.y + bsG.y;
            float ov0 = go.x + xo.x + bsO.x, ov1 = go.y + xo.y + bsO.y;
            if (t == 0) {
                iv0 += crI.x; iv1 += crI.y; fv0 += crF.x; fv1 += crF.y;
                gv0 += crG.x; gv1 += crG.y; ov0 += crO.x; ov1 += crO.y;
            }
            float c0v = sigmoid_(fv0) * cst0 + sigmoid_(iv0) * tanhf_(gv0);
            float c1v = sigmoid_(fv1) * cst1 + sigmoid_(iv1) * tanhf_(gv1);
            cst0 = c0v; cst1 = c1v;
            float h0v = sigmoid_(ov0) * tanhf_(c0v);
            float h1v = sigmoid_(ov1) * tanhf_(c1v);
            __half2 hh2 = __floats2half2_rn(h0v, h1v);
            uint32_t hv = *(uint32_t*)&hh2;
            *(uint32_t*)(g_hall + ((size_t)t * BB + bg) * HH + s * 32 + 2 * up) = hv;
            if (t < LL - 1) {
                uint32_t boff = nxt * HS_BUF, moff = nxt * 8;
#pragma unroll
                for (int r = 0; r < 8; r++)
                    st_async32(rb[r] + boff, hv, rm[r] + moff);
            }
        }

        // x-part MMA for t+1 (fills the DSMEM transit window)
        if (t < LL - 1) {
            float ax0[4] = {0.f, 0.f, 0.f, 0.f};
            float ax1[4] = {0.f, 0.f, 0.f, 0.f};
            const uint32_t aX = smem_u + OFF_XS + nxt * 8448 + aOff;
            uint32_t b0, b1, b2, b3;
#pragma unroll
            for (int kk = 0; kk < 16; kk++) {
                ldsm4(a0, a1, a2, a3, aX + kk * 32);
                ldsm4(b0, b1, b2, b3, bX + kk * 32);
                mma16816(ax0, a0, a1, a2, a3, b0, b1);
                mma16816(ax1, a0, a1, a2, a3, b2, b3);
            }
            float* gxn = (float*)(smem + OFF_GSMX + nxt * 8448);
            *(float2*)(gxn + g * 132 + c0c) = make_float2(ax0[0], ax0[1]);
            *(float2*)(gxn + (g + 8) * 132 + c0c) = make_float2(ax0[2], ax0[3]);
            *(float2*)(gxn + g * 132 + c0c + 8) = make_float2(ax1[0], ax1[1]);
            *(float2*)(gxn + (g + 8) * 132 + c0c + 8) = make_float2(ax1[2], ax1[3]);
        }
    }
    asm volatile("barrier.cluster.arrive.aligned;" ::: "memory");
    asm volatile("barrier.cluster.wait.aligned;" ::: "memory");
}

// ---------------- output projection (launch idx 3): 2 A-tiles per resident B ----
static constexpr int SMEM_OUT = 128 * 264 * 2 + 64 * 264 * 2;

__global__ void __launch_bounds__(256, 1)
out_proj(const float* __restrict__ b_lin, float* __restrict__ out) {
    extern __shared__ char smem[];
    __half* As = (__half*)smem;
    __half* Bsm = (__half*)(smem + 128 * 264 * 2);
    int tid = threadIdx.x;
    int warp = tid >> 5, lane = tid & 31;
    int g = lane >> 2, tig = lane & 3;

    for (int i = tid; i < 64 * 32; i += 256) {
        int row = i >> 5, c8 = i & 31;
        *(uint4*)(Bsm + row * 264 + c8 * 8) =
            *(const uint4*)(g_Wlin16 + row * HH + c8 * 8);
    }

    const uint32_t sm_u = s2u(smem);
    const uint32_t aW = sm_u + warp * 16 * 528 + (lane & 15) * 528 + (lane >> 4) * 16;
    const uint32_t bA = sm_u + 128 * 264 * 2 +
        ((lane & 7) + ((lane >> 4) << 3)) * 528 + (((lane >> 3) & 1) << 4);

#pragma unroll 1
    for (int it = 0; it < 2; it++) {
        size_t r0 = ((size_t)blockIdx.x * 2 + it) * 128;

        for (int i = tid; i < 128 * 32; i += 256) {
            int row = i >> 5, c8 = i & 31;
            *(uint4*)(As + row * 264 + c8 * 8) =
                *(const uint4*)(g_hall + (r0 + row) * HH + c8 * 8);
        }
        __syncthreads();

        float accs[8][4];
#pragma unroll
        for (int j = 0; j < 8; j++)
#pragma unroll
            for (int q = 0; q < 4; q++) accs[j][q] = 0.f;

#pragma unroll 4
        for (int kk = 0; kk < 16; kk++) {
            uint32_t a0, a1, a2, a3;
            ldsm4(a0, a1, a2, a3, aW + kk * 32);
#pragma unroll
            for (int jp = 0; jp < 4; jp++) {
                uint32_t b0, b1, b2, b3;
                ldsm4(b0, b1, b2, b3, bA + jp * 16 * 528 + kk * 32);
                mma16816(accs[2 * jp], a0, a1, a2, a3, b0, b1);
                mma16816(accs[2 * jp + 1], a0, a1, a2, a3, b2, b3);
            }
        }
#pragma unroll
        for (int j = 0; j < 8; j++) {
            int f0 = 8 * j + 2 * tig;
            float bl0 = __ldg(b_lin + f0), bl1 = __ldg(b_lin + f0 + 1);
            size_t r = r0 + 16 * warp + g;
            size_t b = r & 255, t = r >> 8;
            *(float2*)(out + (b * LL + t) * FF + f0) =
                make_float2(accs[j][0] + bl0, accs[j][1] + bl1);
            r += 8; b = r & 255; t = r >> 8;
            *(float2*)(out + (b * LL + t) * FF + f0) =
                make_float2(accs[j][2] + bl0, accs[j][3] + bl1);
        }
        __syncthreads();
    }
}

// ---------------- launch ----------------
extern "C" void kernel_launch(void* const* d_in, const int* in_sizes, int n_in,
                              void* d_out, int out_size) {
    const float* x     = (const float*)d_in[0];
    const float* h0    = (const float*)d_in[1];
    const float* c0    = (const float*)d_in[2];
    const float* W_ih  = (const float*)d_in[4];
    const float* W_hh  = (const float*)d_in[5];
    const float* b_ih  = (const float*)d_in[6];
    const float* b_hh  = (const float*)d_in[7];
    const float* W_lin = (const float*)d_in[8];
    const float* b_lin = (const float*)d_in[9];
    float* out = (float*)d_out;

    cudaFuncSetAttribute(lstm_main, cudaFuncAttributeMaxDynamicSharedMemorySize, SMEM_MAIN);
    cudaFuncSetAttribute(out_proj, cudaFuncAttributeMaxDynamicSharedMemorySize, SMEM_OUT);

    prep_all<<<4164, 256>>>(W_ih, W_hh, W_lin, b_ih, b_hh, b_lin, h0); // idx 0
    prep_corr0<<<32768, 256>>>(W_ih);                                  // idx 1
    lstm_main<<<128, 256, SMEM_MAIN>>>(h0, c0, x);                     // idx 2
    out_proj<<<512, 256, SMEM_OUT>>>(b_lin, out);                      // idx 3
}

// round 17
// speedup vs baseline: 2.2020x; 2.2020x over previous
#include <cuda_runtime.h>
#include <cuda_fp16.h>
#include <cstdint>

#define HH 256
#define FF 64
#define LL 512
#define BB 256

// ---------------- device scratch ----------------
__device__ __half g_Wh[8][128][256];
__device__ __half g_Wx16[1024 * 256];
__device__ __half g_Wlin16[FF * HH];
__device__ float  g_bias[1024];
__device__ float  g_po0[BB][FF];
__device__ float  g_corr0[BB][1024];
__device__ float  g_gx[(size_t)LL * BB * 1024];
__device__ __half g_hall[(size_t)LL * BB * HH];

// ---------------- ptx helpers ----------------
__device__ __forceinline__ void mma16816(float* d, uint32_t a0, uint32_t a1,
                                         uint32_t a2, uint32_t a3,
                                         uint32_t b0, uint32_t b1) {
    asm volatile(
        "mma.sync.aligned.m16n8k16.row.col.f32.f16.f16.f32 "
        "{%0,%1,%2,%3}, {%4,%5,%6,%7}, {%8,%9}, {%0,%1,%2,%3};"
        : "+f"(d[0]), "+f"(d[1]), "+f"(d[2]), "+f"(d[3])
        : "r"(a0), "r"(a1), "r"(a2), "r"(a3), "r"(b0), "r"(b1));
}
__device__ __forceinline__ void ldsm4(uint32_t& r0, uint32_t& r1, uint32_t& r2,
                                      uint32_t& r3, uint32_t a) {
    asm volatile("ldmatrix.sync.aligned.m8n8.x4.shared.b16 {%0,%1,%2,%3}, [%4];"
                 : "=r"(r0), "=r"(r1), "=r"(r2), "=r"(r3) : "r"(a));
}
__device__ __forceinline__ uint32_t s2u(const void* p) {
    uint32_t a;
    asm("{.reg .u64 t; cvta.to.shared.u64 t, %1; cvt.u32.u64 %0, t;}"
        : "=r"(a) : "l"(p));
    return a;
}
__device__ __forceinline__ uint32_t mapa_(uint32_t a, uint32_t r) {
    uint32_t d;
    asm("mapa.shared::cluster.u32 %0, %1, %2;" : "=r"(d) : "r"(a), "r"(r));
    return d;
}
__device__ __forceinline__ void mbar_init(uint32_t a, uint32_t n) {
    asm volatile("mbarrier.init.shared.b64 [%0], %1;" :: "r"(a), "r"(n) : "memory");
}
__device__ __forceinline__ void mbar_expect(uint32_t a, uint32_t tx) {
    asm volatile("mbarrier.arrive.expect_tx.shared.b64 _, [%0], %1;"
                 :: "r"(a), "r"(tx) : "memory");
}
__device__ __forceinline__ void st_async32(uint32_t dst, uint32_t v, uint32_t mb) {
    asm volatile(
        "st.async.shared::cluster.mbarrier::complete_tx::bytes.b32 [%0], %1, [%2];"
        :: "r"(dst), "r"(v), "r"(mb) : "memory");
}
__device__ __forceinline__ void mbar_wait(uint32_t a, uint32_t par) {
    uint32_t done;
    asm volatile(
        "{\n\t.reg .pred p;\n\t"
        "mbarrier.try_wait.parity.acquire.cta.shared::cta.b64 p, [%1], %2;\n\t"
        "selp.b32 %0, 1, 0, p;\n\t}"
        : "=r"(done) : "r"(a), "r"(par) : "memory");
    if (!done) {
        asm volatile(
            "{\n\t.reg .pred P1;\n\t"
            "W_%=:\n\t"
            "mbarrier.try_wait.parity.acquire.cta.shared::cta.b64 P1, [%0], %1, 0x989680;\n\t"
            "@P1 bra.uni D_%=;\n\t"
            "bra.uni W_%=;\n\t"
            "D_%=:\n\t}"
            :: "r"(a), "r"(par) : "memory");
    }
}
__device__ __forceinline__ float tanhf_(float x) {
    float r;
    asm("tanh.approx.f32 %0, %1;" : "=f"(r) : "f"(x));
    return r;
}
__device__ __forceinline__ float sigmoid_(float x) {
    return fmaf(tanhf_(0.5f * x), 0.5f, 0.5f);
}

// ---------------- prep kernels ----------------
__global__ void prep_all(const float* __restrict__ W_ih, const float* __restrict__ W_hh,
                         const float* __restrict__ W_lin, const float* __restrict__ b_ih,
                         const float* __restrict__ b_hh, const float* __restrict__ b_lin,
                         const float* __restrict__ h0) {
    if (blockIdx.x < 2112) {
        int id = blockIdx.x * 256 + threadIdx.x;
        if (id < 262144) {
            int k = id & 255, ln = (id >> 8) & 127, s = id >> 15;
            int n = (ln >> 5) * 256 + s * 32 + (ln & 31);
            float v = W_hh[n * HH + k];
            float acc = 0.f;
#pragma unroll 8
            for (int f = 0; f < FF; f++)
                acc += W_lin[f * HH + k] * W_ih[n * (FF + HH) + f];
            g_Wh[s][ln][k] = __float2half(v + acc);
        } else if (id < 524288) {
            int j = id - 262144;
            int n = j >> 8, k = j & 255;
            g_Wx16[n * 256 + k] = __float2half(W_ih[n * (FF + HH) + FF + k]);
        } else if (id < 540672) {
            g_Wlin16[id - 524288] = __float2half(W_lin[id - 524288]);
        }
    } else if (blockIdx.x < 4160) {
        int wid = (blockIdx.x - 2112) * 8 + (threadIdx.x >> 5);  // po0
        int lane = threadIdx.x & 31;
        int b = wid >> 6, f = wid & 63;
        float acc = 0.f;
#pragma unroll
        for (int q = 0; q < 8; q++) {
            int k = lane + 32 * q;
            acc += h0[b * HH + k] * W_lin[f * HH + k];
        }
#pragma unroll
        for (int o = 16; o; o >>= 1) acc += __shfl_xor_sync(~0u, acc, o);
        if (!lane) g_po0[b][f] = acc + b_lin[f];
    } else {
        int n = (blockIdx.x - 4160) * 256 + threadIdx.x;  // bias
        float v = b_ih[n] + b_hh[n];
#pragma unroll 8
        for (int f = 0; f < FF; f++) v += b_lin[f] * W_ih[n * (FF + HH) + f];
        g_bias[n] = v;
    }
}

__global__ void prep_corr0(const float* __restrict__ W_ih) {
    int wid = blockIdx.x * 8 + (threadIdx.x >> 5);
    int lane = threadIdx.x & 31;
    int b = wid >> 10, n = wid & 1023;
    float acc = W_ih[n * (FF + HH) + lane] * g_po0[b][lane] +
                W_ih[n * (FF + HH) + 32 + lane] * g_po0[b][32 + lane];
#pragma unroll
    for (int o = 16; o; o >>= 1) acc += __shfl_xor_sync(~0u, acc, o);
    if (!lane) g_corr0[b][n] = -acc;
}

// gates_x GEMM (launch idx 2): 2 A-tiles per block share one resident B-tile
static constexpr int SMEM_GX = 128 * 264 * 2 * 2;

__global__ void __launch_bounds__(256, 1)
gemm_x(const float* __restrict__ x) {
    extern __shared__ char smem[];
    int tid = threadIdx.x;
    int warp = tid >> 5, lane = tid & 31;
    int g = lane >> 2, tig = lane & 3;
    int mIdx2 = blockIdx.x >> 3, nIdx = blockIdx.x & 7;
    __half* As = (__half*)smem;
    __half* Bsm = (__half*)(smem + 128 * 264 * 2);

    for (int i = tid; i < 128 * 32; i += 256) {
        int row = i >> 5, c8 = i & 31;
        *(uint4*)(Bsm + row * 264 + c8 * 8) =
            *(const uint4*)(g_Wx16 + (size_t)(nIdx * 128 + row) * 256 + c8 * 8);
    }

    const uint32_t sm_u = s2u(smem);
    const uint32_t aW = sm_u + warp * 16 * 528 + (lane & 15) * 528 + (lane >> 4) * 16;
    const uint32_t bA = sm_u + 128 * 264 * 2 +
        ((lane & 7) + ((lane >> 4) << 3)) * 528 + (((lane >> 3) & 1) << 4);

#pragma unroll 1
    for (int it = 0; it < 2; it++) {
        int mIdx = mIdx2 * 2 + it;
        size_t r0 = (size_t)mIdx * 128;
        int t0 = mIdx >> 1, b0 = (mIdx & 1) * 128;

        for (int i = tid; i < 128 * 64; i += 256) {
            int row = i >> 6, c4 = i & 63;
            float4 v =
                *(const float4*)(x + ((size_t)(b0 + row) * LL + t0) * HH + c4 * 4);
            __half2 h01 = __floats2half2_rn(v.x, v.y);
            __half2 h23 = __floats2half2_rn(v.z, v.w);
            *(uint2*)(As + row * 264 + c4 * 4) =
                make_uint2(*(uint32_t*)&h01, *(uint32_t*)&h23);
        }
        __syncthreads();

        float acc[16][4];
#pragma unroll
        for (int j = 0; j < 16; j++)
#pragma unroll
            for (int q = 0; q < 4; q++) acc[j][q] = 0.f;

#pragma unroll 4
        for (int kk = 0; kk < 16; kk++) {
            uint32_t a0, a1, a2, a3;
            ldsm4(a0, a1, a2, a3, aW + kk * 32);
#pragma unroll
            for (int jp = 0; jp < 8; jp++) {
                uint32_t b0r, b1r, b2r, b3r;
                ldsm4(b0r, b1r, b2r, b3r, bA + jp * 16 * 528 + kk * 32);
                mma16816(acc[2 * jp], a0, a1, a2, a3, b0r, b1r);
                mma16816(acc[2 * jp + 1], a0, a1, a2, a3, b2r, b3r);
            }
        }
#pragma unroll
        for (int j = 0; j < 16; j++) {
            int f0 = 8 * j + 2 * tig;
            int n = nIdx * 128 + f0;
            float2 bl = *(const float2*)(g_bias + n);
            size_t r = r0 + 16 * warp + g;
            float2 v0 = make_float2(acc[j][0] + bl.x, acc[j][1] + bl.y);
            float2 v1 = make_float2(acc[j][2] + bl.x, acc[j][3] + bl.y);
            if (r < 256) {
                float2 c = *(const float2*)(&g_corr0[r][n]);
                v0.x += c.x; v0.y += c.y;
            }
            if (r + 8 < 256) {
                float2 c = *(const float2*)(&g_corr0[r + 8][n]);
                v1.x += c.x; v1.y += c.y;
            }
            *(float2*)(g_gx + (r << 10) + n) = v0;
            *(float2*)(g_gx + ((r + 8) << 10) + n) = v1;
        }
        __syncthreads();
    }
}

// ---------------- main recurrent kernel (launch idx 3) ----------------
// Two independent batch tiles per cluster, interleaved per step to hide
// DSMEM transit. Per-tile protocol byte-identical to the proven R13 one.
static constexpr int OFF_WH   = 0;                       // 67584
static constexpr int HS_BUF   = 8448;                    // 16*528
static constexpr int TILE_HS  = 2 * HS_BUF;              // per-tile (2 phases)
static constexpr int OFF_HS   = 67584;                   // 2 tiles x 2 phases
static constexpr int OFF_GSM  = OFF_HS + 2 * TILE_HS;    // 101376; 4 x 8448
static constexpr int OFF_MBAR = OFF_GSM + 4 * 8448;      // 135168; 4 mbars
static constexpr int SMEM_MAIN = OFF_MBAR + 64;

__global__ void __cluster_dims__(8, 1, 1) __launch_bounds__(256, 1)
lstm_main(const float* __restrict__ h0, const float* __restrict__ c0in) {
    extern __shared__ char smem[];
    __half* Wh_s = (__half*)(smem + OFF_WH);

    const uint32_t smem_u = s2u(smem);
    const uint32_t mbarB = smem_u + OFF_MBAR;  // [A ph0, A ph1, B ph0, B ph1]

    int tid = threadIdx.x;
    int cl = blockIdx.x >> 3, s = blockIdx.x & 7;
    int warp = tid >> 5, lane = tid & 31;
    int mA = cl * 2, mB = cl * 2 + 1;

    if (tid < 4) mbar_init(mbarB + tid * 8, 1);

    for (int i = tid; i < 128 * 32; i += 256) {
        int row = i >> 5, c8 = i & 31;
        *(uint4*)(Wh_s + row * 264 + c8 * 8) = *(const uint4*)(&g_Wh[s][row][c8 * 8]);
    }
    for (int i = tid; i < 2 * 16 * 64; i += 256) {
        int tl = i >> 10, j = i & 1023;
        int row = j >> 6, c4 = j & 63;
        float4 v =
            *(const float4*)(h0 + (size_t)((mA + tl) * 16 + row) * HH + c4 * 4);
        __half* d = (__half*)(smem + OFF_HS + tl * TILE_HS) + row * 264 + c4 * 4;
        d[0] = __float2half(v.x); d[1] = __float2half(v.y);
        d[2] = __float2half(v.z); d[3] = __float2half(v.w);
    }
    int b = tid >> 4, up = tid & 15;
    int bgA = mA * 16 + b, bgB = mB * 16 + b;
    float2 cvA = *(const float2*)(c0in + (size_t)bgA * HH + s * 32 + 2 * up);
    float2 cvB = *(const float2*)(c0in + (size_t)bgB * HH + s * 32 + 2 * up);
    float cA0 = cvA.x, cA1 = cvA.y, cB0 = cvB.x, cB1 = cvB.y;
    __syncthreads();

    uint32_t Bf[16][4];
    {
        const uint32_t bB = smem_u + OFF_WH +
            (16 * warp + (lane & 7) + ((lane >> 4) << 3)) * 528 +
            (((lane >> 3) & 1) << 4);
#pragma unroll
        for (int kk = 0; kk < 16; kk++)
            ldsm4(Bf[kk][0], Bf[kk][1], Bf[kk][2], Bf[kk][3], bB + kk * 32);
    }
    const uint32_t aOff = (lane & 15) * 528 + (lane >> 4) * 16;
    uint32_t rb[8], rm[8];
    {
        uint32_t dstoff = b * 528 + (s * 32 + 2 * up) * 2;
#pragma unroll
        for (int r = 0; r < 8; r++) {
            rb[r] = mapa_(smem_u + OFF_HS, r) + dstoff;
            rm[r] = mapa_(mbarB, r);
        }
    }
    const int g = lane >> 2, tig = lane & 3;
    int phA0 = 0, phA1 = 0, phB0 = 0, phB1 = 0;

    asm volatile("barrier.cluster.arrive.aligned;" ::: "memory");
    asm volatile("barrier.cluster.wait.aligned;" ::: "memory");

#pragma unroll 1
    for (int t = 0; t < LL; t++) {
        const int cur = t & 1, nxt = cur ^ 1;
        if (tid == 0 && t < LL - 1) {
            mbar_expect(mbarB + nxt * 8, 8192);
            mbar_expect(mbarB + 16 + nxt * 8, 8192);
        }

        // ---------------- tile A ----------------
        {
            const float* gxp =
                g_gx + (((size_t)t * BB + bgA) << 10) + s * 32 + 2 * up;
            float2 gxi = *(const float2*)(gxp);
            float2 gxf = *(const float2*)(gxp + 256);
            float2 gxg = *(const float2*)(gxp + 512);
            float2 gxo = *(const float2*)(gxp + 768);
            if (t > 0) {
                if (cur) { mbar_wait(mbarB + 8, (uint32_t)phA1); phA1 ^= 1; }
                else     { mbar_wait(mbarB,     (uint32_t)phA0); phA0 ^= 1; }
            }
            float acc0[4] = {0.f, 0.f, 0.f, 0.f};
            float acc1[4] = {0.f, 0.f, 0.f, 0.f};
            const uint32_t aH = smem_u + OFF_HS + cur * HS_BUF + aOff;
            uint32_t a0, a1, a2, a3;
#pragma unroll
            for (int kk = 0; kk < 16; kk++) {
                ldsm4(a0, a1, a2, a3, aH + kk * 32);
                mma16816(acc0, a0, a1, a2, a3, Bf[kk][0], Bf[kk][1]);
                mma16816(acc1, a0, a1, a2, a3, Bf[kk][2], Bf[kk][3]);
            }
            float* gsmc = (float*)(smem + OFF_GSM + cur * 8448);
            int c0c = 16 * warp + 2 * tig;
            *(float2*)(gsmc + g * 132 + c0c) = make_float2(acc0[0], acc0[1]);
            *(float2*)(gsmc + (g + 8) * 132 + c0c) = make_float2(acc0[2], acc0[3]);
            *(float2*)(gsmc + g * 132 + c0c + 8) = make_float2(acc1[0], acc1[1]);
            *(float2*)(gsmc + (g + 8) * 132 + c0c + 8) = make_float2(acc1[2], acc1[3]);
            __syncthreads();
            float2 gi = *(const float2*)(gsmc + b * 132 + 2 * up);
            float2 gf = *(const float2*)(gsmc + b * 132 + 32 + 2 * up);
            float2 gg = *(const float2*)(gsmc + b * 132 + 64 + 2 * up);
            float2 go = *(const float2*)(gsmc + b * 132 + 96 + 2 * up);
            float c0v = sigmoid_(gf.x + gxf.x) * cA0 +
                        sigmoid_(gi.x + gxi.x) * tanhf_(gg.x + gxg.x);
            float c1v = sigmoid_(gf.y + gxf.y) * cA1 +
                        sigmoid_(gi.y + gxi.y) * tanhf_(gg.y + gxg.y);
            cA0 = c0v; cA1 = c1v;
            float h0v = sigmoid_(go.x + gxo.x) * tanhf_(c0v);
            float h1v = sigmoid_(go.y + gxo.y) * tanhf_(c1v);
            __half2 hh2 = __floats2half2_rn(h0v, h1v);
            uint32_t hv = *(uint32_t*)&hh2;
            *(uint32_t*)(g_hall + ((size_t)t * BB + bgA) * HH + s * 32 + 2 * up) = hv;
            if (t < LL - 1) {
                uint32_t boff = nxt * HS_BUF, moff = nxt * 8;
#pragma unroll
                for (int r = 0; r < 8; r++)
                    st_async32(rb[r] + boff, hv, rm[r] + moff);
            }
        }
        // ---------------- tile B ----------------
        {
            const float* gxp =
                g_gx + (((size_t)t * BB + bgB) << 10) + s * 32 + 2 * up;
            float2 gxi = *(const float2*)(gxp);
            float2 gxf = *(const float2*)(gxp + 256);
            float2 gxg = *(const float2*)(gxp + 512);
            float2 gxo = *(const float2*)(gxp + 768);
            if (t > 0) {
                if (cur) { mbar_wait(mbarB + 24, (uint32_t)phB1); phB1 ^= 1; }
                else     { mbar_wait(mbarB + 16, (uint32_t)phB0); phB0 ^= 1; }
            }
            float acc0[4] = {0.f, 0.f, 0.f, 0.f};
            float acc1[4] = {0.f, 0.f, 0.f, 0.f};
            const uint32_t aH = smem_u + OFF_HS + TILE_HS + cur * HS_BUF + aOff;
            uint32_t a0, a1, a2, a3;
#pragma unroll
            for (int kk = 0; kk < 16; kk++) {
                ldsm4(a0, a1, a2, a3, aH + kk * 32);
                mma16816(acc0, a0, a1, a2, a3, Bf[kk][0], Bf[kk][1]);
                mma16816(acc1, a0, a1, a2, a3, Bf[kk][2], Bf[kk][3]);
            }
            float* gsmc = (float*)(smem + OFF_GSM + (2 + cur) * 8448);
            int c0c = 16 * warp + 2 * tig;
            *(float2*)(gsmc + g * 132 + c0c) = make_float2(acc0[0], acc0[1]);
            *(float2*)(gsmc + (g + 8) * 132 + c0c) = make_float2(acc0[2], acc0[3]);
            *(float2*)(gsmc + g * 132 + c0c + 8) = make_float2(acc1[0], acc1[1]);
            *(float2*)(gsmc + (g + 8) * 132 + c0c + 8) = make_float2(acc1[2], acc1[3]);
            __syncthreads();
            float2 gi = *(const float2*)(gsmc + b * 132 + 2 * up);
            float2 gf = *(const float2*)(gsmc + b * 132 + 32 + 2 * up);
            float2 gg = *(const float2*)(gsmc + b * 132 + 64 + 2 * up);
            float2 go = *(const float2*)(gsmc + b * 132 + 96 + 2 * up);
            float c0v = sigmoid_(gf.x + gxf.x) * cB0 +
                        sigmoid_(gi.x + gxi.x) * tanhf_(gg.x + gxg.x);
            float c1v = sigmoid_(gf.y + gxf.y) * cB1 +
                        sigmoid_(gi.y + gxi.y) * tanhf_(gg.y + gxg.y);
            cB0 = c0v; cB1 = c1v;
            float h0v = sigmoid_(go.x + gxo.x) * tanhf_(c0v);
            float h1v = sigmoid_(go.y + gxo.y) * tanhf_(c1v);
            __half2 hh2 = __floats2half2_rn(h0v, h1v);
            uint32_t hv = *(uint32_t*)&hh2;
            *(uint32_t*)(g_hall + ((size_t)t * BB + bgB) * HH + s * 32 + 2 * up) = hv;
            if (t < LL - 1) {
                uint32_t boff = TILE_HS + nxt * HS_BUF, moff = 16 + nxt * 8;
#pragma unroll
                for (int r = 0; r < 8; r++)
                    st_async32(rb[r] + boff, hv, rm[r] + moff);
            }
        }
    }
    asm volatile("barrier.cluster.arrive.aligned;" ::: "memory");
    asm volatile("barrier.cluster.wait.aligned;" ::: "memory");
}

// ---------------- output projection (launch idx 4): 2 A-tiles per resident B ----
static constexpr int SMEM_OUT = 128 * 264 * 2 + 64 * 264 * 2;

__global__ void __launch_bounds__(256, 1)
out_proj(const float* __restrict__ b_lin, float* __restrict__ out) {
    extern __shared__ char smem[];
    __half* As = (__half*)smem;
    __half* Bsm = (__half*)(smem + 128 * 264 * 2);
    int tid = threadIdx.x;
    int warp = tid >> 5, lane = tid & 31;
    int g = lane >> 2, tig = lane & 3;

    for (int i = tid; i < 64 * 32; i += 256) {
        int row = i >> 5, c8 = i & 31;
        *(uint4*)(Bsm + row * 264 + c8 * 8) =
            *(const uint4*)(g_Wlin16 + row * HH + c8 * 8);
    }

    const uint32_t sm_u = s2u(smem);
    const uint32_t aW = sm_u + warp * 16 * 528 + (lane & 15) * 528 + (lane >> 4) * 16;
    const uint32_t bA = sm_u + 128 * 264 * 2 +
        ((lane & 7) + ((lane >> 4) << 3)) * 528 + (((lane >> 3) & 1) << 4);

#pragma unroll 1
    for (int it = 0; it < 2; it++) {
        size_t r0 = ((size_t)blockIdx.x * 2 + it) * 128;

        for (int i = tid; i < 128 * 32; i += 256) {
            int row = i >> 5, c8 = i & 31;
            *(uint4*)(As + row * 264 + c8 * 8) =
                *(const uint4*)(g_hall + (r0 + row) * HH + c8 * 8);
        }
        __syncthreads();

        float accs[8][4];
#pragma unroll
        for (int j = 0; j < 8; j++)
#pragma unroll
            for (int q = 0; q < 4; q++) accs[j][q] = 0.f;

#pragma unroll 4
        for (int kk = 0; kk < 16; kk++) {
            uint32_t a0, a1, a2, a3;
            ldsm4(a0, a1, a2, a3, aW + kk * 32);
#pragma unroll
            for (int jp = 0; jp < 4; jp++) {
                uint32_t b0, b1, b2, b3;
                ldsm4(b0, b1, b2, b3, bA + jp * 16 * 528 + kk * 32);
                mma16816(accs[2 * jp], a0, a1, a2, a3, b0, b1);
                mma16816(accs[2 * jp + 1], a0, a1, a2, a3, b2, b3);
            }
        }
#pragma unroll
        for (int j = 0; j < 8; j++) {
            int f0 = 8 * j + 2 * tig;
            float bl0 = __ldg(b_lin + f0), bl1 = __ldg(b_lin + f0 + 1);
            size_t r = r0 + 16 * warp + g;
            size_t b = r & 255, t = r >> 8;
            *(float2*)(out + (b * LL + t) * FF + f0) =
                make_float2(accs[j][0] + bl0, accs[j][1] + bl1);
            r += 8; b = r & 255; t = r >> 8;
            *(float2*)(out + (b * LL + t) * FF + f0) =
                make_float2(accs[j][2] + bl0, accs[j][3] + bl1);
        }
        __syncthreads();
    }
}

// ---------------- launch ----------------
extern "C" void kernel_launch(void* const* d_in, const int* in_sizes, int n_in,
                              void* d_out, int out_size) {
    const float* x     = (const float*)d_in[0];
    const float* h0    = (const float*)d_in[1];
    const float* c0    = (const float*)d_in[2];
    const float* W_ih  = (const float*)d_in[4];
    const float* W_hh  = (const float*)d_in[5];
    const float* b_ih  = (const float*)d_in[6];
    const float* b_hh  = (const float*)d_in[7];
    const float* W_lin = (const float*)d_in[8];
    const float* b_lin = (const float*)d_in[9];
    float* out = (float*)d_out;

    cudaFuncSetAttribute(gemm_x, cudaFuncAttributeMaxDynamicSharedMemorySize, SMEM_GX);
    cudaFuncSetAttribute(lstm_main, cudaFuncAttributeMaxDynamicSharedMemorySize, SMEM_MAIN);
    cudaFuncSetAttribute(out_proj, cudaFuncAttributeMaxDynamicSharedMemorySize, SMEM_OUT);

    prep_all<<<4164, 256>>>(W_ih, W_hh, W_lin, b_ih, b_hh, b_lin, h0); // idx 0
    prep_corr0<<<32768, 256>>>(W_ih);                                  // idx 1
    gemm_x<<<4096, 256, SMEM_GX>>>(x);                                 // idx 2
    lstm_main<<<64, 256, SMEM_MAIN>>>(h0, c0);                         // idx 3 <- profiled
    out_proj<<<512, 256, SMEM_OUT>>>(b_lin, out);                      // idx 4
}